// round 1
// baseline (speedup 1.0000x reference)
#include <cuda_runtime.h>
#include <math.h>

// ---------------- problem dims ----------------
#define B_   8
#define T_   16
#define N_   196
#define C_   768
#define H_   8
#define D_   96
#define MEM_ 196
#define HID_ 3072
#define ROWS_ (B_ * N_)          // 1568
#define SCALE_ 0.1020620726159657f  // 96^-0.5

// ---------------- scratch (device globals; no allocation) ----------------
__device__ float g_x   [B_*T_*N_*C_];   // LN'd input
__device__ float g_cat [ROWS_*2*C_];
__device__ float g_hid [ROWS_*HID_];
__device__ float g_cg  [ROWS_*C_];
__device__ float g_memh[ROWS_*C_];
__device__ float g_q   [ROWS_*C_];
__device__ float g_k   [ROWS_*C_];
__device__ float g_o   [B_*H_*N_*MEM_];
__device__ float g_c   [ROWS_*C_];
__device__ float g_c2  [ROWS_*C_];
__device__ float g_gate[B_*H_*MEM_];
__device__ float g_ap  [B_*C_];
__device__ float g_memA[ROWS_*C_];
__device__ float g_memB[ROWS_*C_];

__device__ __forceinline__ float gelu_exact(float x) {
    return 0.5f * x * (1.0f + erff(x * 0.70710678118654752f));
}

// ---------------- LayerNorm over C=768, one block per row ----------------
__global__ __launch_bounds__(256) void ln_kernel(
    const float* __restrict__ x, const float* __restrict__ w,
    const float* __restrict__ b, float* __restrict__ y)
{
    int row = blockIdx.x;
    const float* xr = x + (size_t)row * C_;
    float v[3], s = 0.f, s2 = 0.f;
#pragma unroll
    for (int i = 0; i < 3; i++) {
        v[i] = xr[threadIdx.x + i * 256];
        s += v[i]; s2 += v[i] * v[i];
    }
    __shared__ float red[18];
#pragma unroll
    for (int off = 16; off; off >>= 1) {
        s  += __shfl_down_sync(0xffffffffu, s, off);
        s2 += __shfl_down_sync(0xffffffffu, s2, off);
    }
    int wid = threadIdx.x >> 5, lane = threadIdx.x & 31;
    if (lane == 0) { red[wid] = s; red[8 + wid] = s2; }
    __syncthreads();
    if (threadIdx.x == 0) {
        float ts = 0.f, ts2 = 0.f;
        for (int i = 0; i < 8; i++) { ts += red[i]; ts2 += red[8 + i]; }
        red[16] = ts; red[17] = ts2;
    }
    __syncthreads();
    float mean = red[16] * (1.0f / C_);
    float var  = red[17] * (1.0f / C_) - mean * mean;
    float inv  = rsqrtf(var + 1e-5f);
    float* yr = y + (size_t)row * C_;
#pragma unroll
    for (int i = 0; i < 3; i++) {
        int c = threadIdx.x + i * 256;
        yr[c] = (v[i] - mean) * inv * w[c] + b[c];
    }
}

// ---------------- final: LN(c2 + gate*memh) ----------------
__global__ __launch_bounds__(256) void final_kernel(
    const float* __restrict__ c2, const float* __restrict__ gate,
    const float* __restrict__ memh, const float* __restrict__ w,
    const float* __restrict__ bb, float* __restrict__ y)
{
    int row = blockIdx.x;              // b*MEM + m
    int b = row / MEM_, m = row % MEM_;
    float v[3], s = 0.f, s2 = 0.f;
#pragma unroll
    for (int i = 0; i < 3; i++) {
        int c = threadIdx.x + i * 256;
        float g = gate[(b * H_ + (c / D_)) * MEM_ + m];
        v[i] = c2[(size_t)row * C_ + c] + g * memh[(size_t)row * C_ + c];
        s += v[i]; s2 += v[i] * v[i];
    }
    __shared__ float red[18];
#pragma unroll
    for (int off = 16; off; off >>= 1) {
        s  += __shfl_down_sync(0xffffffffu, s, off);
        s2 += __shfl_down_sync(0xffffffffu, s2, off);
    }
    int wid = threadIdx.x >> 5, lane = threadIdx.x & 31;
    if (lane == 0) { red[wid] = s; red[8 + wid] = s2; }
    __syncthreads();
    if (threadIdx.x == 0) {
        float ts = 0.f, ts2 = 0.f;
        for (int i = 0; i < 8; i++) { ts += red[i]; ts2 += red[8 + i]; }
        red[16] = ts; red[17] = ts2;
    }
    __syncthreads();
    float mean = red[16] * (1.0f / C_);
    float var  = red[17] * (1.0f / C_) - mean * mean;
    float inv  = rsqrtf(var + 1e-5f);
    float* yr = y + (size_t)row * C_;
#pragma unroll
    for (int i = 0; i < 3; i++) {
        int c = threadIdx.x + i * 256;
        yr[c] = (v[i] - mean) * inv * w[c] + bb[c];
    }
}

// ---------------- mem init: copy frame 0 of LN'd x ----------------
__global__ void initmem_kernel(const float* __restrict__ x, float* __restrict__ mem)
{
    int idx = blockIdx.x * 256 + threadIdx.x;
    if (idx >= B_ * MEM_ * C_) return;
    int b = idx / (MEM_ * C_);
    int r = idx % (MEM_ * C_);
    mem[idx] = x[(size_t)b * T_ * N_ * C_ + r];
}

// ---------------- ap = mean over MEM ----------------
__global__ void ap_kernel(const float* __restrict__ mem, float* __restrict__ ap)
{
    int idx = blockIdx.x * 256 + threadIdx.x;  // b*C + c
    if (idx >= B_ * C_) return;
    int b = idx / C_, c = idx % C_;
    float s = 0.f;
    const float* p = mem + (size_t)b * MEM_ * C_ + c;
    for (int m = 0; m < MEM_; m++) s += p[(size_t)m * C_];
    ap[idx] = s * (1.0f / MEM_);
}

// ---------------- cat = [fea(t), broadcast(ap)] ----------------
__global__ void cat_kernel(const float* __restrict__ x, const float* __restrict__ ap,
                           float* __restrict__ cat, int t)
{
    int idx = blockIdx.x * 256 + threadIdx.x;
    if (idx >= ROWS_ * 2 * C_) return;
    int row = idx / (2 * C_), j = idx % (2 * C_);
    int b = row / N_, n = row % N_;
    cat[idx] = (j < C_) ? x[(((size_t)b * T_ + t) * N_ + n) * C_ + j]
                        : ap[b * C_ + (j - C_)];
}

// ---------------- SGEMM 128x128 tile, 8x8 per thread ----------------
__global__ __launch_bounds__(256) void sgemm128(
    const float* __restrict__ A, const float* __restrict__ W,
    const float* __restrict__ bias, float* __restrict__ out,
    int M, int N, int K, int act)
{
    __shared__ float As[16][128];
    __shared__ float Bs[16][128];
    int bm = blockIdx.y * 128, bn = blockIdx.x * 128;
    int tid = threadIdx.x;
    int tx = tid & 15, ty = tid >> 4;
    float acc[8][8];
#pragma unroll
    for (int i = 0; i < 8; i++)
#pragma unroll
        for (int j = 0; j < 8; j++) acc[i][j] = 0.f;
    int aRow = tid >> 2, aCol = (tid & 3) * 4;
    int bRow = tid >> 5, bCol = (tid & 31) * 4;

    for (int k0 = 0; k0 < K; k0 += 16) {
#pragma unroll
        for (int i = 0; i < 2; i++) {
            int r = aRow + i * 64, gr = bm + r;
            float4 v = make_float4(0.f, 0.f, 0.f, 0.f);
            if (gr < M) v = *(const float4*)(A + (size_t)gr * K + k0 + aCol);
            As[aCol + 0][r] = v.x; As[aCol + 1][r] = v.y;
            As[aCol + 2][r] = v.z; As[aCol + 3][r] = v.w;
        }
#pragma unroll
        for (int i = 0; i < 2; i++) {
            int r = bRow + i * 8;
            *(float4*)(&Bs[r][bCol]) = *(const float4*)(W + (size_t)(k0 + r) * N + bn + bCol);
        }
        __syncthreads();
#pragma unroll
        for (int kk = 0; kk < 16; kk++) {
            float a[8], bv[8];
#pragma unroll
            for (int i = 0; i < 8; i++) a[i] = As[kk][ty * 8 + i];
#pragma unroll
            for (int j = 0; j < 8; j++) bv[j] = Bs[kk][tx * 8 + j];
#pragma unroll
            for (int i = 0; i < 8; i++)
#pragma unroll
                for (int j = 0; j < 8; j++) acc[i][j] = fmaf(a[i], bv[j], acc[i][j]);
        }
        __syncthreads();
    }
#pragma unroll
    for (int i = 0; i < 8; i++) {
        int gr = bm + ty * 8 + i;
        if (gr >= M) continue;
#pragma unroll
        for (int j = 0; j < 8; j++) {
            int gc = bn + tx * 8 + j;
            float v = acc[i][j] + bias[gc];
            if (act) v = gelu_exact(v);
            out[(size_t)gr * N + gc] = v;
        }
    }
}

// ---------------- SGEMM 64x64 tile, 4x4 per thread (small N) ----------------
__global__ __launch_bounds__(256) void sgemm64(
    const float* __restrict__ A, const float* __restrict__ W,
    const float* __restrict__ bias, float* __restrict__ out,
    int M, int N, int K, int act)
{
    __shared__ float As[16][64];
    __shared__ float Bs[16][64];
    int bm = blockIdx.y * 64, bn = blockIdx.x * 64;
    int tid = threadIdx.x;
    int tx = tid & 15, ty = tid >> 4;
    float acc[4][4];
#pragma unroll
    for (int i = 0; i < 4; i++)
#pragma unroll
        for (int j = 0; j < 4; j++) acc[i][j] = 0.f;
    int aRow = tid >> 2, aCol = (tid & 3) * 4;
    int bRow = tid >> 4, bCol = (tid & 15) * 4;

    for (int k0 = 0; k0 < K; k0 += 16) {
        {
            int gr = bm + aRow;
            float4 v = make_float4(0.f, 0.f, 0.f, 0.f);
            if (gr < M) v = *(const float4*)(A + (size_t)gr * K + k0 + aCol);
            As[aCol + 0][aRow] = v.x; As[aCol + 1][aRow] = v.y;
            As[aCol + 2][aRow] = v.z; As[aCol + 3][aRow] = v.w;
        }
        *(float4*)(&Bs[bRow][bCol]) = *(const float4*)(W + (size_t)(k0 + bRow) * N + bn + bCol);
        __syncthreads();
#pragma unroll
        for (int kk = 0; kk < 16; kk++) {
            float a[4], bv[4];
#pragma unroll
            for (int i = 0; i < 4; i++) a[i] = As[kk][ty * 4 + i];
#pragma unroll
            for (int j = 0; j < 4; j++) bv[j] = Bs[kk][tx * 4 + j];
#pragma unroll
            for (int i = 0; i < 4; i++)
#pragma unroll
                for (int j = 0; j < 4; j++) acc[i][j] = fmaf(a[i], bv[j], acc[i][j]);
        }
        __syncthreads();
    }
#pragma unroll
    for (int i = 0; i < 4; i++) {
        int gr = bm + ty * 4 + i;
        if (gr >= M) continue;
#pragma unroll
        for (int j = 0; j < 4; j++) {
            int gc = bn + tx * 4 + j;
            float v = acc[i][j] + bias[gc];
            if (act) v = gelu_exact(v);
            out[(size_t)gr * N + gc] = v;
        }
    }
}

// ---------------- attention: o = sigmoid(scale * q.k) per (b,h) ----------------
__global__ __launch_bounds__(256) void attn_kernel(
    const float* __restrict__ q, const float* __restrict__ k, float* __restrict__ o)
{
    int bh = blockIdx.z, b = bh >> 3, h = bh & 7;
    int m0 = blockIdx.x * 32, n0 = blockIdx.y * 32;
    __shared__ float Qs[32][97];
    __shared__ float Ks[32][97];
    for (int idx = threadIdx.x; idx < 32 * 96; idx += 256) {
        int r = idx / 96, d = idx % 96;
        int n = n0 + r;
        Qs[r][d] = (n < N_) ? q[((size_t)b * N_ + n) * C_ + h * D_ + d] : 0.f;
        int m = m0 + r;
        Ks[r][d] = (m < MEM_) ? k[((size_t)b * MEM_ + m) * C_ + h * D_ + d] : 0.f;
    }
    __syncthreads();
    int nl = threadIdx.x & 31, mg = threadIdx.x >> 5;
    float acc[4] = {0.f, 0.f, 0.f, 0.f};
    for (int d = 0; d < 96; d++) {
        float qv = Qs[nl][d];
#pragma unroll
        for (int i = 0; i < 4; i++) acc[i] = fmaf(qv, Ks[mg * 4 + i][d], acc[i]);
    }
    int n = n0 + nl;
    if (n < N_) {
#pragma unroll
        for (int i = 0; i < 4; i++) {
            int m = m0 + mg * 4 + i;
            if (m < MEM_) {
                float v = acc[i] * SCALE_;
                o[(((size_t)b * H_ + h) * N_ + n) * MEM_ + m] = 1.0f / (1.0f + expf(-v));
            }
        }
    }
}

// ---------------- gate[b,h,m] = 1 - mean_n o ----------------
__global__ void gate_kernel(const float* __restrict__ o, float* __restrict__ gate)
{
    int idx = blockIdx.x * 256 + threadIdx.x;   // bh*MEM + m
    if (idx >= B_ * H_ * MEM_) return;
    int m = idx % MEM_, bh = idx / MEM_;
    const float* op = o + (size_t)bh * N_ * MEM_ + m;
    float s = 0.f;
    for (int n = 0; n < N_; n++) s += op[(size_t)n * MEM_];
    gate[idx] = 1.0f - s * (1.0f / N_);
}

// ---------------- c[b,m,hD+d] = sum_n o[b,h,n,m]*cg[b,n,hD+d] ----------------
__global__ __launch_bounds__(256) void cgather_kernel(
    const float* __restrict__ o, const float* __restrict__ cg, float* __restrict__ c)
{
    int bh = blockIdx.y, b = bh >> 3, h = bh & 7;
    int m0 = blockIdx.x * 32;
    int ml = threadIdx.x & 31, dg = threadIdx.x >> 5;   // d = dg*12 .. +11
    __shared__ float Os[32][33];
    __shared__ float Gs[32][97];
    float acc[12];
#pragma unroll
    for (int j = 0; j < 12; j++) acc[j] = 0.f;

    for (int n0 = 0; n0 < N_; n0 += 32) {
        for (int idx = threadIdx.x; idx < 32 * 32; idx += 256) {
            int r = idx >> 5, cc = idx & 31;
            int n = n0 + r, m = m0 + cc;
            Os[r][cc] = (n < N_ && m < MEM_)
                          ? o[(((size_t)b * H_ + h) * N_ + n) * MEM_ + m] : 0.f;
        }
        for (int idx = threadIdx.x; idx < 32 * 96; idx += 256) {
            int r = idx / 96, d = idx % 96;
            int n = n0 + r;
            Gs[r][d] = (n < N_) ? cg[((size_t)b * N_ + n) * C_ + h * D_ + d] : 0.f;
        }
        __syncthreads();
#pragma unroll 8
        for (int nn = 0; nn < 32; nn++) {
            float ov = Os[nn][ml];
#pragma unroll
            for (int j = 0; j < 12; j++) acc[j] = fmaf(ov, Gs[nn][dg * 12 + j], acc[j]);
        }
        __syncthreads();
    }
    int m = m0 + ml;
    if (m < MEM_) {
#pragma unroll
        for (int j = 0; j < 12; j++)
            c[((size_t)b * MEM_ + m) * C_ + h * D_ + dg * 12 + j] = acc[j];
    }
}

// ---------------- host orchestration ----------------
static void launch_gemm(const float* A, const float* W, const float* bias, float* out,
                        int M, int N, int K, int act)
{
    if (N >= 1536) {
        dim3 g(N / 128, (M + 127) / 128);
        sgemm128<<<g, 256>>>(A, W, bias, out, M, N, K, act);
    } else {
        dim3 g(N / 64, (M + 63) / 64);
        sgemm64<<<g, 256>>>(A, W, bias, out, M, N, K, act);
    }
}

extern "C" void kernel_launch(void* const* d_in, const int* in_sizes, int n_in,
                              void* d_out, int out_size)
{
    const float* cur_fea = (const float*)d_in[0];
    const float* n1w = (const float*)d_in[1];
    const float* n1b = (const float*)d_in[2];
    const float* n2w = (const float*)d_in[3];
    const float* n2b = (const float*)d_in[4];
    const float* c_w1 = (const float*)d_in[5];
    const float* c_b1 = (const float*)d_in[6];
    const float* c_w2 = (const float*)d_in[7];
    const float* c_b2 = (const float*)d_in[8];
    const float* m_w1 = (const float*)d_in[9];
    const float* m_b1 = (const float*)d_in[10];
    const float* m_w2 = (const float*)d_in[11];
    const float* m_b2 = (const float*)d_in[12];
    const float* p_w1 = (const float*)d_in[13];
    const float* p_b1 = (const float*)d_in[14];
    const float* p_w2 = (const float*)d_in[15];
    const float* p_b2 = (const float*)d_in[16];
    const float* q_w = (const float*)d_in[17];
    const float* q_b = (const float*)d_in[18];
    const float* k_w = (const float*)d_in[19];
    const float* k_b = (const float*)d_in[20];

    float *x, *cat, *hid, *cg, *memh, *q, *k, *o, *c, *c2, *gate, *ap, *memA, *memB;
    cudaGetSymbolAddress((void**)&x,    g_x);
    cudaGetSymbolAddress((void**)&cat,  g_cat);
    cudaGetSymbolAddress((void**)&hid,  g_hid);
    cudaGetSymbolAddress((void**)&cg,   g_cg);
    cudaGetSymbolAddress((void**)&memh, g_memh);
    cudaGetSymbolAddress((void**)&q,    g_q);
    cudaGetSymbolAddress((void**)&k,    g_k);
    cudaGetSymbolAddress((void**)&o,    g_o);
    cudaGetSymbolAddress((void**)&c,    g_c);
    cudaGetSymbolAddress((void**)&c2,   g_c2);
    cudaGetSymbolAddress((void**)&gate, g_gate);
    cudaGetSymbolAddress((void**)&ap,   g_ap);
    cudaGetSymbolAddress((void**)&memA, g_memA);
    cudaGetSymbolAddress((void**)&memB, g_memB);

    // LN over full input
    ln_kernel<<<B_ * T_ * N_, 256>>>(cur_fea, n1w, n1b, x);
    // init memory = frame 0
    initmem_kernel<<<(B_ * MEM_ * C_ + 255) / 256, 256>>>(x, memA);

    float* mcur = memA;
    float* mnxt = memB;

    for (int t = 1; t < T_; t++) {
        ap_kernel<<<(B_ * C_ + 255) / 256, 256>>>(mcur, ap);
        cat_kernel<<<(ROWS_ * 2 * C_ + 255) / 256, 256>>>(x, ap, cat, t);

        launch_gemm(cat,  c_w1, c_b1, hid,  ROWS_, HID_, 2 * C_, 1);  // fc1_c + gelu
        launch_gemm(hid,  c_w2, c_b2, cg,   ROWS_, C_,   HID_,   0);  // fc2_c
        launch_gemm(mcur, m_w1, m_b1, hid,  ROWS_, HID_, C_,     1);  // fc1_m + gelu
        launch_gemm(hid,  m_w2, m_b2, memh, ROWS_, C_,   HID_,   0);  // fc2_m
        launch_gemm(cg,   q_w,  q_b,  q,    ROWS_, C_,   C_,     0);  // q proj
        launch_gemm(mcur, k_w,  k_b,  k,    ROWS_, C_,   C_,     0);  // k proj

        attn_kernel<<<dim3(7, 7, B_ * H_), 256>>>(q, k, o);
        gate_kernel<<<(B_ * H_ * MEM_ + 255) / 256, 256>>>(o, gate);
        cgather_kernel<<<dim3(7, B_ * H_), 256>>>(o, cg, c);

        launch_gemm(c,   p_w1, p_b1, hid, ROWS_, HID_, C_,   1);      // fc1_p + gelu
        launch_gemm(hid, p_w2, p_b2, c2,  ROWS_, C_,   HID_, 0);      // fc2_p

        float* dst = (t == T_ - 1) ? (float*)d_out : mnxt;
        final_kernel<<<B_ * MEM_, 256>>>(c2, gate, memh, n2w, n2b, dst);

        float* tmp = mcur; mcur = mnxt; mnxt = tmp;
    }
}